// round 1
// baseline (speedup 1.0000x reference)
#include <cuda_runtime.h>
#include <cuda_bf16.h>
#include <math.h>

#define KNODES 16
#define DMODEL 256
#define NSCALE 3
#define TAU_C 0.0001f
#define LN_EPS_C 1e-5f
#define MAXB 1024

// ---------------- scratch (device globals; no allocation allowed) ----------
__device__ float g_xn[MAXB * KNODES * DMODEL];            // 16.8 MB
__device__ float g_P [MAXB * KNODES * KNODES];            // 1 MB
__device__ float g_mats[MAXB * NSCALE * 2 * 256];         // 6.3 MB : per (b,s): L0[256], N[256]
__device__ float g_VX[(size_t)MAXB * KNODES * 1536];      // 100 MB : [V | Xw]
__device__ float g_NE[(size_t)MAXB * KNODES * 1536];      // 100 MB : [nu | eu]
__device__ float g_y [MAXB * KNODES * DMODEL];            // 16.8 MB
__device__ float g_h [MAXB * KNODES * DMODEL];            // 16.8 MB
__device__ float g_F [(size_t)MAXB * KNODES * 1024];      // 67 MB

// ---------------- block-wide sum over 256 threads --------------------------
__device__ __forceinline__ float block_sum_256(float v) {
    __shared__ float red[8];
#pragma unroll
    for (int o = 16; o > 0; o >>= 1) v += __shfl_xor_sync(0xffffffffu, v, o);
    int lane = threadIdx.x & 31, w = threadIdx.x >> 5;
    if (lane == 0) red[w] = v;
    __syncthreads();
    float t = (threadIdx.x < 8) ? red[threadIdx.x] : 0.f;
    if (threadIdx.x < 32) {
#pragma unroll
        for (int o = 4; o > 0; o >>= 1) t += __shfl_xor_sync(0xffffffffu, t, o);
        if (threadIdx.x == 0) red[0] = t;
    }
    __syncthreads();
    float r = red[0];
    __syncthreads();
    return r;
}

// ---------------- LN1 + P = xn @ Wg + bg -----------------------------------
__global__ void ln1_p_kernel(const float* __restrict__ x,
                             const float* __restrict__ g, const float* __restrict__ bb,
                             const float* __restrict__ Wg, const float* __restrict__ bg,
                             float* __restrict__ xn_out, float* __restrict__ P_out) {
    int row = blockIdx.x;           // b*K + k
    int t = threadIdx.x;            // 256 == DMODEL
    float v = x[(size_t)row * DMODEL + t];
    float mean = block_sum_256(v) * (1.f / DMODEL);
    float d = v - mean;
    float var = block_sum_256(d * d) * (1.f / DMODEL);
    float xn = d * rsqrtf(var + LN_EPS_C) * g[t] + bb[t];
    xn_out[(size_t)row * DMODEL + t] = xn;

    __shared__ float sxn[256];
    __shared__ float part[256];
    sxn[t] = xn;
    __syncthreads();
    int c = t & 15, seg = t >> 4;
    float p = 0.f;
    int d0 = seg * 16;
#pragma unroll
    for (int i = 0; i < 16; i++) p += sxn[d0 + i] * Wg[(d0 + i) * 16 + c];
    part[seg * 16 + c] = p;
    __syncthreads();
    if (t < 16) {
        float acc = bg[t];
#pragma unroll
        for (int s = 0; s < 16; s++) acc += part[s * 16 + t];
        P_out[(size_t)row * 16 + t] = acc;
    }
}

// ---------------- plain LN --------------------------------------------------
__global__ void ln_kernel(const float* __restrict__ x,
                          const float* __restrict__ g, const float* __restrict__ bb,
                          float* __restrict__ out) {
    int row = blockIdx.x;
    int t = threadIdx.x;
    float v = x[(size_t)row * DMODEL + t];
    float mean = block_sum_256(v) * (1.f / DMODEL);
    float d = v - mean;
    float var = block_sum_256(d * d) * (1.f / DMODEL);
    out[(size_t)row * DMODEL + t] = d * rsqrtf(var + LN_EPS_C) * g[t] + bb[t];
}

// ---------------- build per-(b,s) 16x16 operators L0, N --------------------
// N = D diag(m) D^T + 4 diag(tw) + TAU*(ABS ABS^T),  D[k,k']=2k-15 (diag) / sign(k'-k)
__global__ void build_mats_kernel(const float* __restrict__ P,
                                  const float* __restrict__ mask,
                                  const float* __restrict__ log_scales,
                                  float* __restrict__ mats) {
    int b = blockIdx.x;
    int tid = threadIdx.x;          // 256
    __shared__ float sP[256];
    __shared__ float sm[16];
    __shared__ float sp2[16];
    __shared__ float sDsq[256];
    __shared__ float saff[256];
    __shared__ float stw[16];
    sP[tid] = P[(size_t)b * 256 + tid];
    if (tid < 16) sm[tid] = mask[(size_t)b * 16 + tid];
    __syncthreads();
    int k = tid >> 4, l = tid & 15;
    if (tid < 16) {
        float s = 0.f;
#pragma unroll
        for (int c = 0; c < 16; c++) s += sP[tid * 16 + c] * sP[tid * 16 + c];
        sp2[tid] = s;
    }
    __syncthreads();
    {
        float dt = 0.f;
#pragma unroll
        for (int c = 0; c < 16; c++) dt += sP[k * 16 + c] * sP[l * 16 + c];
        float d2 = sp2[k] + sp2[l] - 2.f * dt;
        sDsq[tid] = fmaxf(d2, 0.f) * sm[k] * sm[l];
    }
    __syncthreads();
    for (int s = 0; s < NSCALE; s++) {
        float denom = 2.f * expf(2.f * log_scales[s]) + 1e-8f;
        saff[tid] = expf(-sDsq[tid] / denom) * sm[k] * sm[l];
        __syncthreads();
        // L0: graph Laplacian of aff (+TAU I)
        float l0;
        if (k == l) {
            float srow = 0.f;
#pragma unroll
            for (int j = 0; j < 16; j++) if (j != k) srow += saff[k * 16 + j];
            l0 = srow + TAU_C;
        } else {
            l0 = -saff[tid];
        }
        // tw[j] = sum over triangles with middle vertex j
        if (tid < 16) {
            float tsum = 0.f;
            int j = tid;
            for (int i = 0; i < j; i++)
                for (int k2 = j + 1; k2 < 16; k2++)
                    tsum += saff[i * 16 + j] * saff[j * 16 + k2] * saff[i * 16 + k2];
            stw[tid] = tsum;
        }
        __syncthreads();
        // N[k,l]
        float nv = 0.f;
#pragma unroll
        for (int kp = 0; kp < 16; kp++) {
            float dk = (kp == k) ? (2.f * k - 15.f) : ((kp > k) ? 1.f : -1.f);
            float dl = (kp == l) ? (2.f * l - 15.f) : ((kp > l) ? 1.f : -1.f);
            nv += sm[kp] * dk * dl;
        }
        nv += (k == l) ? (4.f * stw[k] + 15.f * TAU_C) : TAU_C;
        size_t base = ((size_t)b * NSCALE + s) * 512;
        mats[base + tid]       = l0;
        mats[base + 256 + tid] = nv;
        __syncthreads();
    }
}

// ---------------- apply 16x16 operators: NE[b,k,c] = sum_l M_s[k,l] VX[b,l,c]
__global__ void apply_mats_kernel(const float* __restrict__ mats,
                                  const float* __restrict__ VX,
                                  float* __restrict__ NE) {
    int b = blockIdx.x;
    int tid = threadIdx.x;          // 256
    __shared__ float sMat[1536];
    __shared__ float sV[16 * 512];
#pragma unroll
    for (int i = tid; i < 1536; i += 256) sMat[i] = mats[(size_t)b * 1536 + i];
    const float* VXb = VX + (size_t)b * KNODES * 1536;
    float* NEb = NE + (size_t)b * KNODES * 1536;
    for (int ch = 0; ch < 3; ch++) {
        int c0 = ch * 512;
        __syncthreads();
        for (int i = tid; i < 8192; i += 256) {
            int l = i >> 9, cc = i & 511;
            sV[l * 512 + cc] = VXb[(size_t)l * 1536 + c0 + cc];
        }
        __syncthreads();
        for (int i = tid; i < 8192; i += 256) {
            int kk = i >> 9, cc = i & 511;
            int c = c0 + cc;
            int s = (c % 768) >> 8;
            const float* Mrow = &sMat[s * 512 + ((c < 768) ? 0 : 256) + kk * 16];
            float acc = 0.f;
#pragma unroll
            for (int l = 0; l < 16; l++) acc += Mrow[l] * sV[l * 512 + cc];
            NEb[(size_t)kk * 1536 + c] = acc;
        }
    }
}

// ---------------- generic tiled SGEMM: C = A(MxKd) @ B(KdxN) + epilogue ----
#define BM 128
#define BN 64
#define BKK 16
__global__ __launch_bounds__(256) void sgemm_kernel(
    const float* __restrict__ A, const float* __restrict__ Bm,
    float* __restrict__ C, const float* __restrict__ bias, float biasScale,
    const float* __restrict__ resid,
    int M, int N, int Kd, int ldc, int ldr, int doGelu) {
    __shared__ float As[BKK][BM];
    __shared__ float Bs[BKK][BN];
    int bm = blockIdx.y * BM;
    int bn = blockIdx.x * BN;
    int tid = threadIdx.x;
    float acc[8][4];
#pragma unroll
    for (int i = 0; i < 8; i++)
#pragma unroll
        for (int j = 0; j < 4; j++) acc[i][j] = 0.f;

    int trow = (tid >> 4) * 8;
    int tcol = (tid & 15) * 4;

    for (int k0 = 0; k0 < Kd; k0 += BKK) {
#pragma unroll
        for (int i = 0; i < 2; i++) {
            int f4 = tid + i * 256;
            int r = f4 >> 2;
            int c4 = (f4 & 3) * 4;
            int gr = bm + r;
            float4 v = make_float4(0.f, 0.f, 0.f, 0.f);
            if (gr < M) v = *(const float4*)(A + (size_t)gr * Kd + k0 + c4);
            As[c4 + 0][r] = v.x; As[c4 + 1][r] = v.y;
            As[c4 + 2][r] = v.z; As[c4 + 3][r] = v.w;
        }
        {
            int r = tid >> 4;
            int c4 = (tid & 15) * 4;
            float4 v = *(const float4*)(Bm + (size_t)(k0 + r) * N + bn + c4);
            Bs[r][c4 + 0] = v.x; Bs[r][c4 + 1] = v.y;
            Bs[r][c4 + 2] = v.z; Bs[r][c4 + 3] = v.w;
        }
        __syncthreads();
#pragma unroll
        for (int kk = 0; kk < BKK; kk++) {
            float ra[8], rb[4];
#pragma unroll
            for (int i = 0; i < 8; i++) ra[i] = As[kk][trow + i];
#pragma unroll
            for (int j = 0; j < 4; j++) rb[j] = Bs[kk][tcol + j];
#pragma unroll
            for (int i = 0; i < 8; i++)
#pragma unroll
                for (int j = 0; j < 4; j++) acc[i][j] += ra[i] * rb[j];
        }
        __syncthreads();
    }
#pragma unroll
    for (int i = 0; i < 8; i++) {
        int m = bm + trow + i;
        if (m >= M) continue;
#pragma unroll
        for (int j = 0; j < 4; j++) {
            int n = bn + tcol + j;
            float v = acc[i][j];
            if (bias) v += biasScale * bias[n];
            if (resid) v += resid[(size_t)m * ldr + n];
            if (doGelu) v = 0.5f * v * (1.0f + erff(v * 0.70710678118654752f));
            C[(size_t)m * ldc + n] = v;
        }
    }
}

// ---------------- launch ----------------------------------------------------
extern "C" void kernel_launch(void* const* d_in, const int* in_sizes, int n_in,
                              void* d_out, int out_size) {
    const float* x          = (const float*)d_in[0];
    const float* mask       = (const float*)d_in[1];
    const float* Wg         = (const float*)d_in[2];
    const float* bg         = (const float*)d_in[3];
    const float* log_scales = (const float*)d_in[4];
    const float* Wv         = (const float*)d_in[5];
    const float* bv         = (const float*)d_in[6];
    const float* We         = (const float*)d_in[7];
    const float* be         = (const float*)d_in[8];
    const float* Wo         = (const float*)d_in[9];
    const float* bo         = (const float*)d_in[10];
    const float* ln1g       = (const float*)d_in[11];
    const float* ln1b       = (const float*)d_in[12];
    const float* ln2g       = (const float*)d_in[13];
    const float* ln2b       = (const float*)d_in[14];
    const float* Wf1        = (const float*)d_in[15];
    const float* bf1        = (const float*)d_in[16];
    const float* Wf2        = (const float*)d_in[17];
    const float* bf2        = (const float*)d_in[18];
    float* out = (float*)d_out;

    int B = in_sizes[0] / (KNODES * DMODEL);
    int M = B * KNODES;

    void *p_xn, *p_P, *p_mats, *p_VX, *p_NE, *p_y, *p_h, *p_F;
    cudaGetSymbolAddress(&p_xn, g_xn);
    cudaGetSymbolAddress(&p_P, g_P);
    cudaGetSymbolAddress(&p_mats, g_mats);
    cudaGetSymbolAddress(&p_VX, g_VX);
    cudaGetSymbolAddress(&p_NE, g_NE);
    cudaGetSymbolAddress(&p_y, g_y);
    cudaGetSymbolAddress(&p_h, g_h);
    cudaGetSymbolAddress(&p_F, g_F);
    float* xn = (float*)p_xn;   float* Pm = (float*)p_P;
    float* mats = (float*)p_mats; float* VX = (float*)p_VX;
    float* NE = (float*)p_NE;   float* y = (float*)p_y;
    float* h = (float*)p_h;     float* F = (float*)p_F;

    // 1. LN1 + P
    ln1_p_kernel<<<M, 256>>>(x, ln1g, ln1b, Wg, bg, xn, Pm);
    // 2. per-(b,s) 16x16 operators
    build_mats_kernel<<<B, 256>>>(Pm, mask, log_scales, mats);
    // 3. V = xn@Wv + bv  (cols 0..767 of VX)
    {
        dim3 g(768 / BN, (M + BM - 1) / BM);
        sgemm_kernel<<<g, 256>>>(xn, Wv, VX, bv, 1.0f, nullptr,
                                 M, 768, 256, 1536, 0, 0);
    }
    // 4. Xw = xn@We + 0.5*be  (cols 768..1535 of VX)
    {
        dim3 g(768 / BN, (M + BM - 1) / BM);
        sgemm_kernel<<<g, 256>>>(xn, We, VX + 768, be, 0.5f, nullptr,
                                 M, 768, 256, 1536, 0, 0);
    }
    // 5. apply L0/N -> NE
    apply_mats_kernel<<<B, 256>>>(mats, VX, NE);
    // 6. y = x + NE@Wo + bo
    {
        dim3 g(256 / BN, (M + BM - 1) / BM);
        sgemm_kernel<<<g, 256>>>(NE, Wo, y, bo, 1.0f, x,
                                 M, 256, 1536, 256, 256, 0);
    }
    // 7. h = LN2(y)
    ln_kernel<<<M, 256>>>(y, ln2g, ln2b, h);
    // 8. F = gelu(h@Wf1 + bf1)
    {
        dim3 g(1024 / BN, (M + BM - 1) / BM);
        sgemm_kernel<<<g, 256>>>(h, Wf1, F, bf1, 1.0f, nullptr,
                                 M, 1024, 256, 1024, 0, 1);
    }
    // 9. out = y + F@Wf2 + bf2
    {
        dim3 g(256 / BN, (M + BM - 1) / BM);
        sgemm_kernel<<<g, 256>>>(F, Wf2, out, bf2, 1.0f, y,
                                 M, 256, 1024, 256, 256, 0);
    }
}

// round 4
// speedup vs baseline: 1.8333x; 1.8333x over previous
#include <cuda_runtime.h>
#include <cuda_bf16.h>
#include <cstdint>
#include <math.h>

#define KNODES 16
#define DMODEL 256
#define NSCALE 3
#define TAU_C 0.0001f
#define LN_EPS_C 1e-5f
#define MAXB 1024

// ---------------- scratch (device globals; no allocation allowed) ----------
__device__ float g_xn[MAXB * KNODES * DMODEL];            // 16.8 MB
__device__ float g_P [MAXB * KNODES * KNODES];            // 1 MB
__device__ float g_mats[MAXB * NSCALE * 2 * 256];         // 6.3 MB : per (b,s): L0[256], N[256]
__device__ float g_VX[(size_t)MAXB * KNODES * 1536];      // 100 MB : [V | Xw]
__device__ float g_NE[(size_t)MAXB * KNODES * 1536];      // 100 MB : [nu | eu]
__device__ float g_y [MAXB * KNODES * DMODEL];            // 16.8 MB
__device__ float g_h [MAXB * KNODES * DMODEL];            // 16.8 MB
__device__ float g_F [(size_t)MAXB * KNODES * 1024];      // 67 MB

// ---------------- helpers ---------------------------------------------------
__device__ __forceinline__ uint32_t f2tf32(float f) {
    uint32_t r;
    asm("cvt.rna.tf32.f32 %0, %1;" : "=r"(r) : "f"(f));
    return r;
}

__device__ __forceinline__ float block_sum_256(float v) {
    __shared__ float red[8];
#pragma unroll
    for (int o = 16; o > 0; o >>= 1) v += __shfl_xor_sync(0xffffffffu, v, o);
    int lane = threadIdx.x & 31, w = threadIdx.x >> 5;
    if (lane == 0) red[w] = v;
    __syncthreads();
    float t = (threadIdx.x < 8) ? red[threadIdx.x] : 0.f;
    if (threadIdx.x < 32) {
#pragma unroll
        for (int o = 4; o > 0; o >>= 1) t += __shfl_xor_sync(0xffffffffu, t, o);
        if (threadIdx.x == 0) red[0] = t;
    }
    __syncthreads();
    float r = red[0];
    __syncthreads();
    return r;
}

// ---------------- LN1 + P = xn @ Wg + bg -----------------------------------
__global__ void ln1_p_kernel(const float* __restrict__ x,
                             const float* __restrict__ g, const float* __restrict__ bb,
                             const float* __restrict__ Wg, const float* __restrict__ bg,
                             float* __restrict__ xn_out, float* __restrict__ P_out) {
    int row = blockIdx.x;           // b*K + k
    int t = threadIdx.x;            // 256 == DMODEL
    float v = x[(size_t)row * DMODEL + t];
    float mean = block_sum_256(v) * (1.f / DMODEL);
    float d = v - mean;
    float var = block_sum_256(d * d) * (1.f / DMODEL);
    float xn = d * rsqrtf(var + LN_EPS_C) * g[t] + bb[t];
    xn_out[(size_t)row * DMODEL + t] = xn;

    __shared__ float sxn[256];
    __shared__ float part[256];
    sxn[t] = xn;
    __syncthreads();
    int c = t & 15, seg = t >> 4;
    float p = 0.f;
    int d0 = seg * 16;
#pragma unroll
    for (int i = 0; i < 16; i++) p += sxn[d0 + i] * Wg[(d0 + i) * 16 + c];
    part[seg * 16 + c] = p;
    __syncthreads();
    if (t < 16) {
        float acc = bg[t];
#pragma unroll
        for (int s = 0; s < 16; s++) acc += part[s * 16 + t];
        P_out[(size_t)row * 16 + t] = acc;
    }
}

// ---------------- plain LN --------------------------------------------------
__global__ void ln_kernel(const float* __restrict__ x,
                          const float* __restrict__ g, const float* __restrict__ bb,
                          float* __restrict__ out) {
    int row = blockIdx.x;
    int t = threadIdx.x;
    float v = x[(size_t)row * DMODEL + t];
    float mean = block_sum_256(v) * (1.f / DMODEL);
    float d = v - mean;
    float var = block_sum_256(d * d) * (1.f / DMODEL);
    out[(size_t)row * DMODEL + t] = d * rsqrtf(var + LN_EPS_C) * g[t] + bb[t];
}

// ---------------- build per-(b,s) 16x16 operators L0, N --------------------
__global__ void build_mats_kernel(const float* __restrict__ P,
                                  const float* __restrict__ mask,
                                  const float* __restrict__ log_scales,
                                  float* __restrict__ mats) {
    int b = blockIdx.x;
    int tid = threadIdx.x;          // 256
    __shared__ float sP[256];
    __shared__ float sm[16];
    __shared__ float sp2[16];
    __shared__ float sDsq[256];
    __shared__ float saff[256];
    __shared__ float stw[16];
    sP[tid] = P[(size_t)b * 256 + tid];
    if (tid < 16) sm[tid] = mask[(size_t)b * 16 + tid];
    __syncthreads();
    int k = tid >> 4, l = tid & 15;
    if (tid < 16) {
        float s = 0.f;
#pragma unroll
        for (int c = 0; c < 16; c++) s += sP[tid * 16 + c] * sP[tid * 16 + c];
        sp2[tid] = s;
    }
    __syncthreads();
    {
        float dt = 0.f;
#pragma unroll
        for (int c = 0; c < 16; c++) dt += sP[k * 16 + c] * sP[l * 16 + c];
        float d2 = sp2[k] + sp2[l] - 2.f * dt;
        sDsq[tid] = fmaxf(d2, 0.f) * sm[k] * sm[l];
    }
    __syncthreads();
    for (int s = 0; s < NSCALE; s++) {
        float denom = 2.f * expf(2.f * log_scales[s]) + 1e-8f;
        saff[tid] = expf(-sDsq[tid] / denom) * sm[k] * sm[l];
        __syncthreads();
        float l0;
        if (k == l) {
            float srow = 0.f;
#pragma unroll
            for (int j = 0; j < 16; j++) if (j != k) srow += saff[k * 16 + j];
            l0 = srow + TAU_C;
        } else {
            l0 = -saff[tid];
        }
        if (tid < 16) {
            float tsum = 0.f;
            int j = tid;
            for (int i = 0; i < j; i++)
                for (int k2 = j + 1; k2 < 16; k2++)
                    tsum += saff[i * 16 + j] * saff[j * 16 + k2] * saff[i * 16 + k2];
            stw[tid] = tsum;
        }
        __syncthreads();
        float nv = 0.f;
#pragma unroll
        for (int kp = 0; kp < 16; kp++) {
            float dk = (kp == k) ? (2.f * k - 15.f) : ((kp > k) ? 1.f : -1.f);
            float dl = (kp == l) ? (2.f * l - 15.f) : ((kp > l) ? 1.f : -1.f);
            nv += sm[kp] * dk * dl;
        }
        nv += (k == l) ? (4.f * stw[k] + 15.f * TAU_C) : TAU_C;
        size_t base = ((size_t)b * NSCALE + s) * 512;
        mats[base + tid]       = l0;
        mats[base + 256 + tid] = nv;
        __syncthreads();
    }
}

// ---------------- apply 16x16 operators ------------------------------------
__global__ void apply_mats_kernel(const float* __restrict__ mats,
                                  const float* __restrict__ VX,
                                  float* __restrict__ NE) {
    int b = blockIdx.x;
    int tid = threadIdx.x;          // 256
    __shared__ float sMat[1536];
    __shared__ float sV[16 * 512];
#pragma unroll
    for (int i = tid; i < 1536; i += 256) sMat[i] = mats[(size_t)b * 1536 + i];
    const float* VXb = VX + (size_t)b * KNODES * 1536;
    float* NEb = NE + (size_t)b * KNODES * 1536;
    for (int ch = 0; ch < 3; ch++) {
        int c0 = ch * 512;
        __syncthreads();
        for (int i = tid; i < 8192; i += 256) {
            int l = i >> 9, cc = i & 511;
            sV[l * 512 + cc] = VXb[(size_t)l * 1536 + c0 + cc];
        }
        __syncthreads();
        for (int i = tid; i < 8192; i += 256) {
            int kk = i >> 9, cc = i & 511;
            int c = c0 + cc;
            int s = (c % 768) >> 8;
            const float* Mrow = &sMat[s * 512 + ((c < 768) ? 0 : 256) + kk * 16];
            float acc = 0.f;
#pragma unroll
            for (int l = 0; l < 16; l++) acc += Mrow[l] * sV[l * 512 + cc];
            NEb[(size_t)kk * 1536 + c] = acc;
        }
    }
}

// ---------------- tf32 tensor-core GEMM ------------------------------------
// C(MxN) = A(MxKd) @ B(KdxN) [+ biasScale*bias] [+ resid] [gelu]
// block tile 128x128, BK=32, 8 warps of 64x32 (4x4 m16n8k8 tiles)
__global__ __launch_bounds__(256) void tf32_gemm_kernel(
    const float* __restrict__ A, const float* __restrict__ Bm,
    float* __restrict__ C, const float* __restrict__ bias, float biasScale,
    const float* __restrict__ resid,
    int M, int N, int Kd, int ldc, int ldr, int doGelu) {
    __shared__ uint32_t As[32][136];   // [k][m], stride 136 -> frag reads conflict-free
    __shared__ uint32_t Bs[32][132];   // [k][n]

    const int tid  = threadIdx.x;
    const int warp = tid >> 5, lane = tid & 31;
    const int g = lane >> 2, t = lane & 3;
    const int wm = (warp & 1) << 6;    // 0 / 64
    const int wn = (warp >> 1) << 5;   // 0..96
    const int bm = blockIdx.y << 7;
    const int bn = blockIdx.x << 7;

    // A staging: thread covers row ra, k-halfchunk kh (16 floats = 4 float4)
    const int ra = tid & 127;
    const int kh = (tid >> 7) << 4;
    const bool arow_ok = (bm + ra) < M;
    const float* Aptr = A + (size_t)(bm + ra) * Kd + kh;
    // B staging: per i, row (i*8 + warp), cols lane*4..+3
    const float* Bptr = Bm + (size_t)warp * N + bn + lane * 4;

    float c[4][4][4];
#pragma unroll
    for (int i = 0; i < 4; i++)
#pragma unroll
        for (int j = 0; j < 4; j++)
#pragma unroll
            for (int r = 0; r < 4; r++) c[i][j][r] = 0.f;

    float4 pa[4], pb[4];
    // prefetch k0 = 0
#pragma unroll
    for (int i = 0; i < 4; i++)
        pa[i] = arow_ok ? *(const float4*)(Aptr + i * 4)
                        : make_float4(0.f, 0.f, 0.f, 0.f);
#pragma unroll
    for (int i = 0; i < 4; i++)
        pb[i] = *(const float4*)(Bptr + (size_t)(i * 8) * N);

    for (int k0 = 0; k0 < Kd; k0 += 32) {
        __syncthreads();   // previous compute finished using smem
        // store staged chunk (tf32-converted)
#pragma unroll
        for (int i = 0; i < 4; i++) {
            As[kh + i * 4 + 0][ra] = f2tf32(pa[i].x);
            As[kh + i * 4 + 1][ra] = f2tf32(pa[i].y);
            As[kh + i * 4 + 2][ra] = f2tf32(pa[i].z);
            As[kh + i * 4 + 3][ra] = f2tf32(pa[i].w);
        }
#pragma unroll
        for (int i = 0; i < 4; i++) {
            uint4 bv;
            bv.x = f2tf32(pb[i].x); bv.y = f2tf32(pb[i].y);
            bv.z = f2tf32(pb[i].z); bv.w = f2tf32(pb[i].w);
            *(uint4*)&Bs[i * 8 + warp][lane * 4] = bv;
        }
        __syncthreads();
        // prefetch next chunk
        if (k0 + 32 < Kd) {
#pragma unroll
            for (int i = 0; i < 4; i++)
                pa[i] = arow_ok ? *(const float4*)(Aptr + k0 + 32 + i * 4)
                                : make_float4(0.f, 0.f, 0.f, 0.f);
#pragma unroll
            for (int i = 0; i < 4; i++)
                pb[i] = *(const float4*)(Bptr + (size_t)(k0 + 32 + i * 8) * N);
        }
        // compute 4 k-steps of 8
#pragma unroll
        for (int kc = 0; kc < 4; kc++) {
            const int kr = kc * 8 + t;
            uint32_t af[4][4], bf[4][2];
#pragma unroll
            for (int i = 0; i < 4; i++) {
                int m = wm + i * 16 + g;
                af[i][0] = As[kr][m];
                af[i][1] = As[kr][m + 8];
                af[i][2] = As[kr + 4][m];
                af[i][3] = As[kr + 4][m + 8];
            }
#pragma unroll
            for (int j = 0; j < 4; j++) {
                int n = wn + j * 8 + g;
                bf[j][0] = Bs[kr][n];
                bf[j][1] = Bs[kr + 4][n];
            }
#pragma unroll
            for (int i = 0; i < 4; i++)
#pragma unroll
                for (int j = 0; j < 4; j++) {
                    asm volatile(
                        "mma.sync.aligned.m16n8k8.row.col.f32.tf32.tf32.f32 "
                        "{%0,%1,%2,%3}, {%4,%5,%6,%7}, {%8,%9}, {%0,%1,%2,%3};"
                        : "+f"(c[i][j][0]), "+f"(c[i][j][1]),
                          "+f"(c[i][j][2]), "+f"(c[i][j][3])
                        : "r"(af[i][0]), "r"(af[i][1]), "r"(af[i][2]), "r"(af[i][3]),
                          "r"(bf[j][0]), "r"(bf[j][1]));
                }
        }
    }

    // epilogue
#pragma unroll
    for (int i = 0; i < 4; i++) {
        int m0 = bm + wm + i * 16 + g;
#pragma unroll
        for (int j = 0; j < 4; j++) {
            int n0 = bn + wn + j * 8 + 2 * t;
#pragma unroll
            for (int rr = 0; rr < 2; rr++) {
                int m = m0 + rr * 8;
                if (m >= M) continue;
                float v0 = c[i][j][rr * 2 + 0];
                float v1 = c[i][j][rr * 2 + 1];
                if (bias) {
                    v0 += biasScale * bias[n0];
                    v1 += biasScale * bias[n0 + 1];
                }
                if (resid) {
                    v0 += resid[(size_t)m * ldr + n0];
                    v1 += resid[(size_t)m * ldr + n0 + 1];
                }
                if (doGelu) {
                    v0 = 0.5f * v0 * (1.0f + erff(v0 * 0.70710678118654752f));
                    v1 = 0.5f * v1 * (1.0f + erff(v1 * 0.70710678118654752f));
                }
                *(float2*)(C + (size_t)m * ldc + n0) = make_float2(v0, v1);
            }
        }
    }
}

// ---------------- launch ----------------------------------------------------
extern "C" void kernel_launch(void* const* d_in, const int* in_sizes, int n_in,
                              void* d_out, int out_size) {
    const float* x          = (const float*)d_in[0];
    const float* mask       = (const float*)d_in[1];
    const float* Wg         = (const float*)d_in[2];
    const float* bg         = (const float*)d_in[3];
    const float* log_scales = (const float*)d_in[4];
    const float* Wv         = (const float*)d_in[5];
    const float* bv         = (const float*)d_in[6];
    const float* We         = (const float*)d_in[7];
    const float* be         = (const float*)d_in[8];
    const float* Wo         = (const float*)d_in[9];
    const float* bo         = (const float*)d_in[10];
    const float* ln1g       = (const float*)d_in[11];
    const float* ln1b       = (const float*)d_in[12];
    const float* ln2g       = (const float*)d_in[13];
    const float* ln2b       = (const float*)d_in[14];
    const float* Wf1        = (const float*)d_in[15];
    const float* bf1        = (const float*)d_in[16];
    const float* Wf2        = (const float*)d_in[17];
    const float* bf2        = (const float*)d_in[18];
    float* out = (float*)d_out;

    int B = in_sizes[0] / (KNODES * DMODEL);
    int M = B * KNODES;
    int gy = (M + 127) / 128;

    void *p_xn, *p_P, *p_mats, *p_VX, *p_NE, *p_y, *p_h, *p_F;
    cudaGetSymbolAddress(&p_xn, g_xn);
    cudaGetSymbolAddress(&p_P, g_P);
    cudaGetSymbolAddress(&p_mats, g_mats);
    cudaGetSymbolAddress(&p_VX, g_VX);
    cudaGetSymbolAddress(&p_NE, g_NE);
    cudaGetSymbolAddress(&p_y, g_y);
    cudaGetSymbolAddress(&p_h, g_h);
    cudaGetSymbolAddress(&p_F, g_F);
    float* xn = (float*)p_xn;   float* Pm = (float*)p_P;
    float* mats = (float*)p_mats; float* VX = (float*)p_VX;
    float* NE = (float*)p_NE;   float* y = (float*)p_y;
    float* h = (float*)p_h;     float* F = (float*)p_F;

    // 1. LN1 + P
    ln1_p_kernel<<<M, 256>>>(x, ln1g, ln1b, Wg, bg, xn, Pm);
    // 2. per-(b,s) 16x16 operators
    build_mats_kernel<<<B, 256>>>(Pm, mask, log_scales, mats);
    // 3. V = xn@Wv + bv   (cols 0..767 of VX)
    tf32_gemm_kernel<<<dim3(768 / 128, gy), 256>>>(xn, Wv, VX, bv, 1.0f, nullptr,
                                                   M, 768, 256, 1536, 0, 0);
    // 4. Xw = xn@We + 0.5*be  (cols 768..1535 of VX)
    tf32_gemm_kernel<<<dim3(768 / 128, gy), 256>>>(xn, We, VX + 768, be, 0.5f, nullptr,
                                                   M, 768, 256, 1536, 0, 0);
    // 5. apply L0/N -> NE
    apply_mats_kernel<<<B, 256>>>(mats, VX, NE);
    // 6. y = x + NE@Wo + bo
    tf32_gemm_kernel<<<dim3(256 / 128, gy), 256>>>(NE, Wo, y, bo, 1.0f, x,
                                                   M, 256, 1536, 256, 256, 0);
    // 7. h = LN2(y)
    ln_kernel<<<M, 256>>>(y, ln2g, ln2b, h);
    // 8. F = gelu(h@Wf1 + bf1)
    tf32_gemm_kernel<<<dim3(1024 / 128, gy), 256>>>(h, Wf1, F, bf1, 1.0f, nullptr,
                                                    M, 1024, 256, 1024, 0, 1);
    // 9. out = y + F@Wf2 + bf2
    tf32_gemm_kernel<<<dim3(256 / 128, gy), 256>>>(F, Wf2, out, bf2, 1.0f, y,
                                                   M, 256, 1024, 256, 256, 0);
}

// round 5
// speedup vs baseline: 2.6731x; 1.4581x over previous
#include <cuda_runtime.h>
#include <cuda_bf16.h>
#include <cstdint>
#include <math.h>

#define KNODES 16
#define DMODEL 256
#define NSCALE 3
#define TAU_C 0.0001f
#define LN_EPS_C 1e-5f
#define MAXB 1024

// weight segment offsets in g_Wc
#define OFF_WV 0
#define OFF_WE 196608
#define OFF_WO 393216
#define OFF_WF1 786432
#define OFF_WF2 1048576
#define WTOT 1310720

// ---------------- scratch (device globals; no allocation allowed) ----------
__device__ float g_xn[MAXB * KNODES * DMODEL];
__device__ float g_P [MAXB * KNODES * KNODES];
__device__ float g_mats[MAXB * NSCALE * 2 * 256];
__device__ float g_VX[(size_t)MAXB * KNODES * 1536];
__device__ float g_NE[(size_t)MAXB * KNODES * 1536];
__device__ float g_y [MAXB * KNODES * DMODEL];
__device__ float g_h [MAXB * KNODES * DMODEL];
__device__ float g_F [(size_t)MAXB * KNODES * 1024];
__device__ float g_Wc[WTOT];

// ---------------- helpers ---------------------------------------------------
__device__ __forceinline__ uint32_t f2tf32(float f) {
    uint32_t r;
    asm("cvt.rna.tf32.f32 %0, %1;" : "=r"(r) : "f"(f));
    return r;
}
__device__ __forceinline__ float tf32r(float f) {
    return __uint_as_float(f2tf32(f));
}
__device__ __forceinline__ uint32_t su32(const void* p) {
    return (uint32_t)__cvta_generic_to_shared(p);
}

__device__ __forceinline__ float block_sum_256(float v) {
    __shared__ float red[8];
#pragma unroll
    for (int o = 16; o > 0; o >>= 1) v += __shfl_xor_sync(0xffffffffu, v, o);
    int lane = threadIdx.x & 31, w = threadIdx.x >> 5;
    if (lane == 0) red[w] = v;
    __syncthreads();
    float t = (threadIdx.x < 8) ? red[threadIdx.x] : 0.f;
    if (threadIdx.x < 32) {
#pragma unroll
        for (int o = 4; o > 0; o >>= 1) t += __shfl_xor_sync(0xffffffffu, t, o);
        if (threadIdx.x == 0) red[0] = t;
    }
    __syncthreads();
    float r = red[0];
    __syncthreads();
    return r;
}

// ---------------- convert weights to tf32-rounded copy ----------------------
__global__ void convert_w_kernel(const float* __restrict__ Wv, const float* __restrict__ We,
                                 const float* __restrict__ Wo, const float* __restrict__ Wf1,
                                 const float* __restrict__ Wf2, float* __restrict__ Wc) {
    int i = blockIdx.x * 256 + threadIdx.x;
    if (i >= WTOT) return;
    float v;
    if (i < OFF_WE)       v = Wv[i];
    else if (i < OFF_WO)  v = We[i - OFF_WE];
    else if (i < OFF_WF1) v = Wo[i - OFF_WO];
    else if (i < OFF_WF2) v = Wf1[i - OFF_WF1];
    else                  v = Wf2[i - OFF_WF2];
    Wc[i] = tf32r(v);
}

// ---------------- LN1 + P = xn @ Wg + bg  (xn stored tf32-rounded) ----------
__global__ void ln1_p_kernel(const float* __restrict__ x,
                             const float* __restrict__ g, const float* __restrict__ bb,
                             const float* __restrict__ Wg, const float* __restrict__ bg,
                             float* __restrict__ xn_out, float* __restrict__ P_out) {
    int row = blockIdx.x;
    int t = threadIdx.x;
    float v = x[(size_t)row * DMODEL + t];
    float mean = block_sum_256(v) * (1.f / DMODEL);
    float d = v - mean;
    float var = block_sum_256(d * d) * (1.f / DMODEL);
    float xn = d * rsqrtf(var + LN_EPS_C) * g[t] + bb[t];
    xn_out[(size_t)row * DMODEL + t] = tf32r(xn);

    __shared__ float sxn[256];
    __shared__ float part[256];
    sxn[t] = xn;
    __syncthreads();
    int c = t & 15, seg = t >> 4;
    float p = 0.f;
    int d0 = seg * 16;
#pragma unroll
    for (int i = 0; i < 16; i++) p += sxn[d0 + i] * Wg[(d0 + i) * 16 + c];
    part[seg * 16 + c] = p;
    __syncthreads();
    if (t < 16) {
        float acc = bg[t];
#pragma unroll
        for (int s = 0; s < 16; s++) acc += part[s * 16 + t];
        P_out[(size_t)row * 16 + t] = acc;
    }
}

// ---------------- plain LN (output tf32-rounded: feeds GEMM) ----------------
__global__ void ln_kernel(const float* __restrict__ x,
                          const float* __restrict__ g, const float* __restrict__ bb,
                          float* __restrict__ out) {
    int row = blockIdx.x;
    int t = threadIdx.x;
    float v = x[(size_t)row * DMODEL + t];
    float mean = block_sum_256(v) * (1.f / DMODEL);
    float d = v - mean;
    float var = block_sum_256(d * d) * (1.f / DMODEL);
    out[(size_t)row * DMODEL + t] = tf32r(d * rsqrtf(var + LN_EPS_C) * g[t] + bb[t]);
}

// ---------------- build per-(b,s) 16x16 operators L0, N --------------------
__global__ void build_mats_kernel(const float* __restrict__ P,
                                  const float* __restrict__ mask,
                                  const float* __restrict__ log_scales,
                                  float* __restrict__ mats) {
    int b = blockIdx.x;
    int tid = threadIdx.x;
    __shared__ float sP[256];
    __shared__ float sm[16];
    __shared__ float sp2[16];
    __shared__ float sDsq[256];
    __shared__ float saff[256];
    __shared__ float stw[16];
    sP[tid] = P[(size_t)b * 256 + tid];
    if (tid < 16) sm[tid] = mask[(size_t)b * 16 + tid];
    __syncthreads();
    int k = tid >> 4, l = tid & 15;
    if (tid < 16) {
        float s = 0.f;
#pragma unroll
        for (int c = 0; c < 16; c++) s += sP[tid * 16 + c] * sP[tid * 16 + c];
        sp2[tid] = s;
    }
    __syncthreads();
    {
        float dt = 0.f;
#pragma unroll
        for (int c = 0; c < 16; c++) dt += sP[k * 16 + c] * sP[l * 16 + c];
        float d2 = sp2[k] + sp2[l] - 2.f * dt;
        sDsq[tid] = fmaxf(d2, 0.f) * sm[k] * sm[l];
    }
    __syncthreads();
    for (int s = 0; s < NSCALE; s++) {
        float denom = 2.f * expf(2.f * log_scales[s]) + 1e-8f;
        saff[tid] = expf(-sDsq[tid] / denom) * sm[k] * sm[l];
        __syncthreads();
        float l0;
        if (k == l) {
            float srow = 0.f;
#pragma unroll
            for (int j = 0; j < 16; j++) if (j != k) srow += saff[k * 16 + j];
            l0 = srow + TAU_C;
        } else {
            l0 = -saff[tid];
        }
        if (tid < 16) {
            float tsum = 0.f;
            int j = tid;
            for (int i = 0; i < j; i++)
                for (int k2 = j + 1; k2 < 16; k2++)
                    tsum += saff[i * 16 + j] * saff[j * 16 + k2] * saff[i * 16 + k2];
            stw[tid] = tsum;
        }
        __syncthreads();
        float nv = 0.f;
#pragma unroll
        for (int kp = 0; kp < 16; kp++) {
            float dk = (kp == k) ? (2.f * k - 15.f) : ((kp > k) ? 1.f : -1.f);
            float dl = (kp == l) ? (2.f * l - 15.f) : ((kp > l) ? 1.f : -1.f);
            nv += sm[kp] * dk * dl;
        }
        nv += (k == l) ? (4.f * stw[k] + 15.f * TAU_C) : TAU_C;
        size_t base = ((size_t)b * NSCALE + s) * 512;
        mats[base + tid]       = l0;
        mats[base + 256 + tid] = nv;
        __syncthreads();
    }
}

// ---------------- apply 16x16 operators (output tf32-rounded) ---------------
__global__ void apply_mats_kernel(const float* __restrict__ mats,
                                  const float* __restrict__ VX,
                                  float* __restrict__ NE) {
    int b = blockIdx.x;
    int tid = threadIdx.x;
    __shared__ float sMat[1536];
    __shared__ float sV[16 * 512];
#pragma unroll
    for (int i = tid; i < 1536; i += 256) sMat[i] = mats[(size_t)b * 1536 + i];
    const float* VXb = VX + (size_t)b * KNODES * 1536;
    float* NEb = NE + (size_t)b * KNODES * 1536;
    for (int ch = 0; ch < 3; ch++) {
        int c0 = ch * 512;
        __syncthreads();
        for (int i = tid; i < 8192; i += 256) {
            int l = i >> 9, cc = i & 511;
            sV[l * 512 + cc] = VXb[(size_t)l * 1536 + c0 + cc];
        }
        __syncthreads();
        for (int i = tid; i < 8192; i += 256) {
            int kk = i >> 9, cc = i & 511;
            int c = c0 + cc;
            int s = (c % 768) >> 8;
            const float* Mrow = &sMat[s * 512 + ((c < 768) ? 0 : 256) + kk * 16];
            float acc = 0.f;
#pragma unroll
            for (int l = 0; l < 16; l++) acc += Mrow[l] * sV[l * 512 + cc];
            NEb[(size_t)kk * 1536 + c] = tf32r(acc);
        }
    }
}

// ---------------- tf32 GEMM, cp.async double-buffered -----------------------
// C(MxN) = A(MxKd) @ B(KdxN) [+ s*bias] [+ resid] [gelu] [tf32-round output]
// block 128x128, 8 warps of 64x32 (4x4 m16n8k8). All inputs pre-rounded tf32.
#define ASTRIDE 36
#define BSTRIDE 136

__global__ __launch_bounds__(256, 2) void tf32_gemm2(
    const float* __restrict__ A,
    const float* __restrict__ B1, const float* __restrict__ B2,
    int N1, int ldb,
    float* __restrict__ C,
    const float* __restrict__ bias1, const float* __restrict__ bias2,
    float s1, float s2,
    const float* __restrict__ resid,
    int M, int Kd, int ldc, int ldr, int doGelu, int roundOut)
{
    extern __shared__ uint32_t sm_[];
    uint32_t (*As)[128][ASTRIDE] = (uint32_t (*)[128][ASTRIDE])sm_;
    uint32_t (*Bs)[32][BSTRIDE]  = (uint32_t (*)[32][BSTRIDE])(sm_ + 2 * 128 * ASTRIDE);

    const int tid  = threadIdx.x;
    const int warp = tid >> 5, lane = tid & 31;
    const int g = lane >> 2, t = lane & 3;
    const int wm = (warp & 1) << 6;
    const int wn = (warp >> 1) << 5;
    const int bm = blockIdx.y << 7;
    const int bnG = blockIdx.x << 7;

    const float* Bm; const float* bias; float bsc; int bcol;
    if (bnG < N1) { Bm = B1; bias = bias1; bsc = s1; bcol = bnG; }
    else          { Bm = B2; bias = bias2; bsc = s2; bcol = bnG - N1; }

    float acc[4][4][4];
#pragma unroll
    for (int i = 0; i < 4; i++)
#pragma unroll
        for (int j = 0; j < 4; j++)
#pragma unroll
            for (int r = 0; r < 4; r++) acc[i][j][r] = 0.f;

    const int nCh = Kd >> 5;

#define STAGE(sbuf, k0) do {                                                     \
    _Pragma("unroll")                                                            \
    for (int i_ = 0; i_ < 4; i_++) {                                             \
        int q_ = tid + (i_ << 8);                                                \
        int r_ = q_ >> 3, kk_ = q_ & 7;                                          \
        int row_ = bm + r_;                                                      \
        int nb_ = (row_ < M) ? 16 : 0;                                           \
        if (row_ >= M) row_ = M - 1;                                             \
        const float* src_ = A + (size_t)row_ * Kd + (k0) + (kk_ << 2);           \
        uint32_t dst_ = su32(&As[sbuf][r_][kk_ << 2]);                           \
        asm volatile("cp.async.cg.shared.global [%0], [%1], 16, %2;"             \
                     :: "r"(dst_), "l"(src_), "r"(nb_));                         \
    }                                                                            \
    _Pragma("unroll")                                                            \
    for (int i_ = 0; i_ < 4; i_++) {                                             \
        int q_ = tid + (i_ << 8);                                                \
        int r_ = q_ >> 5, cc_ = (q_ & 31) << 2;                                  \
        const float* src_ = Bm + (size_t)((k0) + r_) * ldb + bcol + cc_;         \
        uint32_t dst_ = su32(&Bs[sbuf][r_][cc_]);                                \
        asm volatile("cp.async.cg.shared.global [%0], [%1], 16;"                 \
                     :: "r"(dst_), "l"(src_));                                   \
    }                                                                            \
    asm volatile("cp.async.commit_group;");                                      \
} while (0)

    STAGE(0, 0);

    for (int ch = 0; ch < nCh; ch++) {
        const int s = ch & 1;
        asm volatile("cp.async.wait_group 0;" ::: "memory");
        __syncthreads();
        if (ch + 1 < nCh) STAGE(s ^ 1, (ch + 1) << 5);

#pragma unroll
        for (int kc = 0; kc < 4; kc++) {
            const int kr = (kc << 3) + t;
            uint32_t af[4][4], bf[4][2];
#pragma unroll
            for (int i = 0; i < 4; i++) {
                int m = wm + (i << 4) + g;
                af[i][0] = As[s][m][kr];
                af[i][1] = As[s][m + 8][kr];
                af[i][2] = As[s][m][kr + 4];
                af[i][3] = As[s][m + 8][kr + 4];
            }
#pragma unroll
            for (int j = 0; j < 4; j++) {
                int n = wn + (j << 3) + g;
                bf[j][0] = Bs[s][kr][n];
                bf[j][1] = Bs[s][kr + 4][n];
            }
#pragma unroll
            for (int i = 0; i < 4; i++)
#pragma unroll
                for (int j = 0; j < 4; j++) {
                    asm volatile(
                        "mma.sync.aligned.m16n8k8.row.col.f32.tf32.tf32.f32 "
                        "{%0,%1,%2,%3}, {%4,%5,%6,%7}, {%8,%9}, {%0,%1,%2,%3};"
                        : "+f"(acc[i][j][0]), "+f"(acc[i][j][1]),
                          "+f"(acc[i][j][2]), "+f"(acc[i][j][3])
                        : "r"(af[i][0]), "r"(af[i][1]), "r"(af[i][2]), "r"(af[i][3]),
                          "r"(bf[j][0]), "r"(bf[j][1]));
                }
        }
    }
#undef STAGE

    // epilogue
#pragma unroll
    for (int i = 0; i < 4; i++) {
        int m0 = bm + wm + (i << 4) + g;
#pragma unroll
        for (int j = 0; j < 4; j++) {
            int n0 = bnG + wn + (j << 3) + 2 * t;
            int nb = wn + (j << 3) + 2 * t;   // col within this B region for bias
            (void)nb;
#pragma unroll
            for (int rr = 0; rr < 2; rr++) {
                int m = m0 + rr * 8;
                if (m >= M) continue;
                float v0 = acc[i][j][rr * 2 + 0];
                float v1 = acc[i][j][rr * 2 + 1];
                if (bias) {
                    int bc = bcol + wn + (j << 3) + 2 * t;
                    v0 += bsc * bias[bc];
                    v1 += bsc * bias[bc + 1];
                }
                if (resid) {
                    v0 += resid[(size_t)m * ldr + n0];
                    v1 += resid[(size_t)m * ldr + n0 + 1];
                }
                if (doGelu) {
                    v0 = 0.5f * v0 * (1.0f + erff(v0 * 0.70710678118654752f));
                    v1 = 0.5f * v1 * (1.0f + erff(v1 * 0.70710678118654752f));
                }
                if (roundOut) { v0 = tf32r(v0); v1 = tf32r(v1); }
                *(float2*)(C + (size_t)m * ldc + n0) = make_float2(v0, v1);
            }
        }
    }
}

// ---------------- launch ----------------------------------------------------
extern "C" void kernel_launch(void* const* d_in, const int* in_sizes, int n_in,
                              void* d_out, int out_size) {
    const float* x          = (const float*)d_in[0];
    const float* mask       = (const float*)d_in[1];
    const float* Wg         = (const float*)d_in[2];
    const float* bg         = (const float*)d_in[3];
    const float* log_scales = (const float*)d_in[4];
    const float* Wv         = (const float*)d_in[5];
    const float* bv         = (const float*)d_in[6];
    const float* We         = (const float*)d_in[7];
    const float* be         = (const float*)d_in[8];
    const float* Wo         = (const float*)d_in[9];
    const float* bo         = (const float*)d_in[10];
    const float* ln1g       = (const float*)d_in[11];
    const float* ln1b       = (const float*)d_in[12];
    const float* ln2g       = (const float*)d_in[13];
    const float* ln2b       = (const float*)d_in[14];
    const float* Wf1        = (const float*)d_in[15];
    const float* bf1        = (const float*)d_in[16];
    const float* Wf2        = (const float*)d_in[17];
    const float* bf2        = (const float*)d_in[18];
    float* out = (float*)d_out;

    int B = in_sizes[0] / (KNODES * DMODEL);
    int M = B * KNODES;
    int gy = (M + 127) / 128;

    void *p_xn, *p_P, *p_mats, *p_VX, *p_NE, *p_y, *p_h, *p_F, *p_Wc;
    cudaGetSymbolAddress(&p_xn, g_xn);
    cudaGetSymbolAddress(&p_P, g_P);
    cudaGetSymbolAddress(&p_mats, g_mats);
    cudaGetSymbolAddress(&p_VX, g_VX);
    cudaGetSymbolAddress(&p_NE, g_NE);
    cudaGetSymbolAddress(&p_y, g_y);
    cudaGetSymbolAddress(&p_h, g_h);
    cudaGetSymbolAddress(&p_F, g_F);
    cudaGetSymbolAddress(&p_Wc, g_Wc);
    float* xn = (float*)p_xn;   float* Pm = (float*)p_P;
    float* mats = (float*)p_mats; float* VX = (float*)p_VX;
    float* NE = (float*)p_NE;   float* y = (float*)p_y;
    float* h = (float*)p_h;     float* F = (float*)p_F;
    float* Wc = (float*)p_Wc;

    const int smemBytes = (2 * 128 * ASTRIDE + 2 * 32 * BSTRIDE) * 4;  // 71680
    static int attrDone = 0;
    if (!attrDone) {
        cudaFuncSetAttribute(tf32_gemm2, cudaFuncAttributeMaxDynamicSharedMemorySize, smemBytes);
        attrDone = 1;
    }

    const int BIGN = 1 << 28;

    // 0. tf32-round weights into g_Wc
    convert_w_kernel<<<(WTOT + 255) / 256, 256>>>(Wv, We, Wo, Wf1, Wf2, Wc);
    // 1. LN1 + P
    ln1_p_kernel<<<M, 256>>>(x, ln1g, ln1b, Wg, bg, xn, Pm);
    // 2. per-(b,s) 16x16 operators
    build_mats_kernel<<<B, 256>>>(Pm, mask, log_scales, mats);
    // 3+4. VX = [xn@Wv + bv | xn@We + 0.5*be]   (merged, N=1536)
    tf32_gemm2<<<dim3(12, gy), 256, smemBytes>>>(
        xn, Wc + OFF_WV, Wc + OFF_WE, 768, 768,
        VX, bv, be, 1.0f, 0.5f, nullptr,
        M, 256, 1536, 0, 0, 1);
    // 5. apply L0/N -> NE
    apply_mats_kernel<<<B, 256>>>(mats, VX, NE);
    // 6. y = x + NE@Wo + bo
    tf32_gemm2<<<dim3(2, gy), 256, smemBytes>>>(
        NE, Wc + OFF_WO, Wc + OFF_WO, BIGN, 256,
        y, bo, bo, 1.0f, 1.0f, x,
        M, 1536, 256, 256, 0, 0);
    // 7. h = LN2(y)
    ln_kernel<<<M, 256>>>(y, ln2g, ln2b, h);
    // 8. F = gelu(h@Wf1 + bf1)
    tf32_gemm2<<<dim3(8, gy), 256, smemBytes>>>(
        h, Wc + OFF_WF1, Wc + OFF_WF1, BIGN, 1024,
        F, bf1, bf1, 1.0f, 1.0f, nullptr,
        M, 256, 1024, 0, 1, 1);
    // 9. out = y + F@Wf2 + bf2
    tf32_gemm2<<<dim3(2, gy), 256, smemBytes>>>(
        F, Wc + OFF_WF2, Wc + OFF_WF2, BIGN, 256,
        out, bf2, bf2, 1.0f, 1.0f, y,
        M, 1024, 256, 256, 0, 0);
}

// round 6
// speedup vs baseline: 2.7588x; 1.0321x over previous
#include <cuda_runtime.h>
#include <cuda_bf16.h>
#include <cstdint>
#include <math.h>

#define KNODES 16
#define DMODEL 256
#define NSCALE 3
#define TAU_C 0.0001f
#define LN_EPS_C 1e-5f
#define MAXB 1024

// weight segment offsets in g_Wc
#define OFF_WV 0
#define OFF_WE 196608
#define OFF_WO 393216
#define OFF_WF1 786432
#define OFF_WF2 1048576
#define WTOT 1310720

// ---------------- scratch (device globals; no allocation allowed) ----------
__device__ float g_xn[MAXB * KNODES * DMODEL];
__device__ float g_P [MAXB * KNODES * KNODES];
__device__ float g_mats[MAXB * NSCALE * 2 * 256];
__device__ float g_NE[(size_t)MAXB * KNODES * 1536];
__device__ float g_y [MAXB * KNODES * DMODEL];
__device__ float g_h [MAXB * KNODES * DMODEL];
__device__ float g_F [(size_t)MAXB * KNODES * 1024];
__device__ float g_Wc[WTOT];

// ---------------- helpers ---------------------------------------------------
__device__ __forceinline__ uint32_t f2tf32(float f) {
    uint32_t r;
    asm("cvt.rna.tf32.f32 %0, %1;" : "=r"(r) : "f"(f));
    return r;
}
__device__ __forceinline__ float tf32r(float f) {
    return __uint_as_float(f2tf32(f));
}
__device__ __forceinline__ uint32_t su32(const void* p) {
    return (uint32_t)__cvta_generic_to_shared(p);
}

__device__ __forceinline__ float block_sum_256(float v) {
    __shared__ float red[8];
#pragma unroll
    for (int o = 16; o > 0; o >>= 1) v += __shfl_xor_sync(0xffffffffu, v, o);
    int lane = threadIdx.x & 31, w = threadIdx.x >> 5;
    if (lane == 0) red[w] = v;
    __syncthreads();
    float t = (threadIdx.x < 8) ? red[threadIdx.x] : 0.f;
    if (threadIdx.x < 32) {
#pragma unroll
        for (int o = 4; o > 0; o >>= 1) t += __shfl_xor_sync(0xffffffffu, t, o);
        if (threadIdx.x == 0) red[0] = t;
    }
    __syncthreads();
    float r = red[0];
    __syncthreads();
    return r;
}

// ---------------- convert weights to tf32-rounded copy ----------------------
__global__ void convert_w_kernel(const float* __restrict__ Wv, const float* __restrict__ We,
                                 const float* __restrict__ Wo, const float* __restrict__ Wf1,
                                 const float* __restrict__ Wf2, float* __restrict__ Wc) {
    int i = blockIdx.x * 256 + threadIdx.x;
    if (i >= WTOT) return;
    float v;
    if (i < OFF_WE)       v = Wv[i];
    else if (i < OFF_WO)  v = We[i - OFF_WE];
    else if (i < OFF_WF1) v = Wo[i - OFF_WO];
    else if (i < OFF_WF2) v = Wf1[i - OFF_WF1];
    else                  v = Wf2[i - OFF_WF2];
    Wc[i] = tf32r(v);
}

// ---------------- LN1 + P = xn @ Wg + bg  (xn stored tf32-rounded) ----------
__global__ void ln1_p_kernel(const float* __restrict__ x,
                             const float* __restrict__ g, const float* __restrict__ bb,
                             const float* __restrict__ Wg, const float* __restrict__ bg,
                             float* __restrict__ xn_out, float* __restrict__ P_out) {
    int row = blockIdx.x;
    int t = threadIdx.x;
    float v = x[(size_t)row * DMODEL + t];
    float mean = block_sum_256(v) * (1.f / DMODEL);
    float d = v - mean;
    float var = block_sum_256(d * d) * (1.f / DMODEL);
    float xn = d * rsqrtf(var + LN_EPS_C) * g[t] + bb[t];
    xn_out[(size_t)row * DMODEL + t] = tf32r(xn);

    __shared__ float sxn[256];
    __shared__ float part[256];
    sxn[t] = xn;
    __syncthreads();
    int c = t & 15, seg = t >> 4;
    float p = 0.f;
    int d0 = seg * 16;
#pragma unroll
    for (int i = 0; i < 16; i++) p += sxn[d0 + i] * Wg[(d0 + i) * 16 + c];
    part[seg * 16 + c] = p;
    __syncthreads();
    if (t < 16) {
        float acc = bg[t];
#pragma unroll
        for (int s = 0; s < 16; s++) acc += part[s * 16 + t];
        P_out[(size_t)row * 16 + t] = acc;
    }
}

// ---------------- plain LN (output tf32-rounded: feeds GEMM) ----------------
__global__ void ln_kernel(const float* __restrict__ x,
                          const float* __restrict__ g, const float* __restrict__ bb,
                          float* __restrict__ out) {
    int row = blockIdx.x;
    int t = threadIdx.x;
    float v = x[(size_t)row * DMODEL + t];
    float mean = block_sum_256(v) * (1.f / DMODEL);
    float d = v - mean;
    float var = block_sum_256(d * d) * (1.f / DMODEL);
    out[(size_t)row * DMODEL + t] = tf32r(d * rsqrtf(var + LN_EPS_C) * g[t] + bb[t]);
}

// ---------------- build per-(b,s) 16x16 operators L0, N --------------------
__global__ void build_mats_kernel(const float* __restrict__ P,
                                  const float* __restrict__ mask,
                                  const float* __restrict__ log_scales,
                                  float* __restrict__ mats) {
    int b = blockIdx.x;
    int tid = threadIdx.x;
    __shared__ float sP[256];
    __shared__ float sm[16];
    __shared__ float sp2[16];
    __shared__ float sDsq[256];
    __shared__ float saff[256];
    __shared__ float stw[16];
    sP[tid] = P[(size_t)b * 256 + tid];
    if (tid < 16) sm[tid] = mask[(size_t)b * 16 + tid];
    __syncthreads();
    int k = tid >> 4, l = tid & 15;
    if (tid < 16) {
        float s = 0.f;
#pragma unroll
        for (int c = 0; c < 16; c++) s += sP[tid * 16 + c] * sP[tid * 16 + c];
        sp2[tid] = s;
    }
    __syncthreads();
    {
        float dt = 0.f;
#pragma unroll
        for (int c = 0; c < 16; c++) dt += sP[k * 16 + c] * sP[l * 16 + c];
        float d2 = sp2[k] + sp2[l] - 2.f * dt;
        sDsq[tid] = fmaxf(d2, 0.f) * sm[k] * sm[l];
    }
    __syncthreads();
    for (int s = 0; s < NSCALE; s++) {
        float denom = 2.f * expf(2.f * log_scales[s]) + 1e-8f;
        saff[tid] = expf(-sDsq[tid] / denom) * sm[k] * sm[l];
        __syncthreads();
        float l0;
        if (k == l) {
            float srow = 0.f;
#pragma unroll
            for (int j = 0; j < 16; j++) if (j != k) srow += saff[k * 16 + j];
            l0 = srow + TAU_C;
        } else {
            l0 = -saff[tid];
        }
        if (tid < 16) {
            float tsum = 0.f;
            int j = tid;
            for (int i = 0; i < j; i++)
                for (int k2 = j + 1; k2 < 16; k2++)
                    tsum += saff[i * 16 + j] * saff[j * 16 + k2] * saff[i * 16 + k2];
            stw[tid] = tsum;
        }
        __syncthreads();
        float nv = 0.f;
#pragma unroll
        for (int kp = 0; kp < 16; kp++) {
            float dk = (kp == k) ? (2.f * k - 15.f) : ((kp > k) ? 1.f : -1.f);
            float dl = (kp == l) ? (2.f * l - 15.f) : ((kp > l) ? 1.f : -1.f);
            nv += sm[kp] * dk * dl;
        }
        nv += (k == l) ? (4.f * stw[k] + 15.f * TAU_C) : TAU_C;
        size_t base = ((size_t)b * NSCALE + s) * 512;
        mats[base + tid]       = l0;
        mats[base + 256 + tid] = nv;
        __syncthreads();
    }
}

// ---------------- tf32 GEMM, cp.async double-buffered -----------------------
// C(MxN) = A(MxKd) @ B(KdxN) [+ s*bias] [+ resid] [gelu] [tf32-round output]
// applyMats: epilogue computes C[b*16+r, c] = tf32r( sum_l M_{b,grp(c)}[r,l] *
//            (acc[b*16+l, c] + bias) )  — fuses the 16x16 Hodge operators.
#define ASTRIDE 36
#define BSTRIDE 136
// dynamic smem: mainloop buffers 17920 u32; epilogue tile 128*132=16896 + 2048 mats
#define SMEM_U32 18944

__global__ __launch_bounds__(256, 2) void tf32_gemm2(
    const float* __restrict__ A,
    const float* __restrict__ B1, const float* __restrict__ B2,
    int N1, int ldb,
    float* __restrict__ C,
    const float* __restrict__ bias1, const float* __restrict__ bias2,
    float s1, float s2,
    const float* __restrict__ resid,
    const float* __restrict__ matsG, int applyMats,
    int M, int Kd, int ldc, int ldr, int doGelu, int roundOut)
{
    extern __shared__ uint32_t sm_[];
    uint32_t (*As)[128][ASTRIDE] = (uint32_t (*)[128][ASTRIDE])sm_;
    uint32_t (*Bs)[32][BSTRIDE]  = (uint32_t (*)[32][BSTRIDE])(sm_ + 2 * 128 * ASTRIDE);

    const int tid  = threadIdx.x;
    const int warp = tid >> 5, lane = tid & 31;
    const int g = lane >> 2, t = lane & 3;
    const int wm = (warp & 1) << 6;
    const int wn = (warp >> 1) << 5;
    const int bm = blockIdx.y << 7;
    const int bnG = blockIdx.x << 7;

    const float* Bm; const float* bias; float bsc; int bcol;
    if (bnG < N1) { Bm = B1; bias = bias1; bsc = s1; bcol = bnG; }
    else          { Bm = B2; bias = bias2; bsc = s2; bcol = bnG - N1; }

    float acc[4][4][4];
#pragma unroll
    for (int i = 0; i < 4; i++)
#pragma unroll
        for (int j = 0; j < 4; j++)
#pragma unroll
            for (int r = 0; r < 4; r++) acc[i][j][r] = 0.f;

    const int nCh = Kd >> 5;

#define STAGE(sbuf, k0) do {                                                     \
    _Pragma("unroll")                                                            \
    for (int i_ = 0; i_ < 4; i_++) {                                             \
        int q_ = tid + (i_ << 8);                                                \
        int r_ = q_ >> 3, kk_ = q_ & 7;                                          \
        int row_ = bm + r_;                                                      \
        int nb_ = (row_ < M) ? 16 : 0;                                           \
        if (row_ >= M) row_ = M - 1;                                             \
        const float* src_ = A + (size_t)row_ * Kd + (k0) + (kk_ << 2);           \
        uint32_t dst_ = su32(&As[sbuf][r_][kk_ << 2]);                           \
        asm volatile("cp.async.cg.shared.global [%0], [%1], 16, %2;"             \
                     :: "r"(dst_), "l"(src_), "r"(nb_));                         \
    }                                                                            \
    _Pragma("unroll")                                                            \
    for (int i_ = 0; i_ < 4; i_++) {                                             \
        int q_ = tid + (i_ << 8);                                                \
        int r_ = q_ >> 5, cc_ = (q_ & 31) << 2;                                  \
        const float* src_ = Bm + (size_t)((k0) + r_) * ldb + bcol + cc_;         \
        uint32_t dst_ = su32(&Bs[sbuf][r_][cc_]);                                \
        asm volatile("cp.async.cg.shared.global [%0], [%1], 16;"                 \
                     :: "r"(dst_), "l"(src_));                                   \
    }                                                                            \
    asm volatile("cp.async.commit_group;");                                      \
} while (0)

    STAGE(0, 0);

    for (int ch = 0; ch < nCh; ch++) {
        const int s = ch & 1;
        asm volatile("cp.async.wait_group 0;" ::: "memory");
        __syncthreads();
        if (ch + 1 < nCh) STAGE(s ^ 1, (ch + 1) << 5);

#pragma unroll
        for (int kc = 0; kc < 4; kc++) {
            const int kr = (kc << 3) + t;
            uint32_t af[4][4], bf[4][2];
#pragma unroll
            for (int i = 0; i < 4; i++) {
                int m = wm + (i << 4) + g;
                af[i][0] = As[s][m][kr];
                af[i][1] = As[s][m + 8][kr];
                af[i][2] = As[s][m][kr + 4];
                af[i][3] = As[s][m + 8][kr + 4];
            }
#pragma unroll
            for (int j = 0; j < 4; j++) {
                int n = wn + (j << 3) + g;
                bf[j][0] = Bs[s][kr][n];
                bf[j][1] = Bs[s][kr + 4][n];
            }
#pragma unroll
            for (int i = 0; i < 4; i++)
#pragma unroll
                for (int j = 0; j < 4; j++) {
                    asm volatile(
                        "mma.sync.aligned.m16n8k8.row.col.f32.tf32.tf32.f32 "
                        "{%0,%1,%2,%3}, {%4,%5,%6,%7}, {%8,%9}, {%0,%1,%2,%3};"
                        : "+f"(acc[i][j][0]), "+f"(acc[i][j][1]),
                          "+f"(acc[i][j][2]), "+f"(acc[i][j][3])
                        : "r"(af[i][0]), "r"(af[i][1]), "r"(af[i][2]), "r"(af[i][3]),
                          "r"(bf[j][0]), "r"(bf[j][1]));
                }
        }
    }
#undef STAGE

    if (applyMats) {
        // fused 16x16 operator application epilogue
        float (*Cs)[132] = (float (*)[132])sm_;
        float* matS = (float*)(sm_ + 128 * 132);
        __syncthreads();   // done with As/Bs
        // stage biased accumulators into smem tile
#pragma unroll
        for (int i = 0; i < 4; i++) {
            int ml = wm + (i << 4) + g;
#pragma unroll
            for (int j = 0; j < 4; j++) {
                int nl = wn + (j << 3) + 2 * t;
                int bc = bcol + nl;
                float b0v = bias ? bsc * bias[bc]     : 0.f;
                float b1v = bias ? bsc * bias[bc + 1] : 0.f;
#pragma unroll
                for (int rr = 0; rr < 2; rr++) {
                    Cs[ml + rr * 8][nl]     = acc[i][j][rr * 2 + 0] + b0v;
                    Cs[ml + rr * 8][nl + 1] = acc[i][j][rr * 2 + 1] + b1v;
                }
            }
        }
        // load the 8 per-batch 16x16 matrices for this column group
        int isN = (bnG >= 768) ? 1 : 0;
        int sgrp = (isN ? (bnG - 768) : bnG) >> 8;
        int b0 = bm >> 4;
        __syncthreads();
        for (int i = tid; i < 2048; i += 256) {
            int bb = i >> 8, e = i & 255;
            matS[i] = matsG[((size_t)(b0 + bb) * NSCALE + sgrp) * 512 + (isN << 8) + e];
        }
        __syncthreads();
        // each warp handles one batch; thread handles 4 single-column passes
        int bb = tid >> 5, cs = tid & 31;
        const float* Mb = matS + (bb << 8);
        int growBase = bm + (bb << 4);
        if (growBase < M) {
#pragma unroll
            for (int p = 0; p < 4; p++) {
                int c0 = cs + (p << 5);
                float outv[16];
#pragma unroll
                for (int r = 0; r < 16; r++) outv[r] = 0.f;
#pragma unroll
                for (int l = 0; l < 16; l++) {
                    float vl = Cs[(bb << 4) + l][c0];
#pragma unroll
                    for (int r = 0; r < 16; r++)
                        outv[r] += Mb[(r << 4) + l] * vl;
                }
#pragma unroll
                for (int r = 0; r < 16; r++)
                    C[(size_t)(growBase + r) * ldc + bnG + c0] = tf32r(outv[r]);
            }
        }
        return;
    }

    // generic epilogue
#pragma unroll
    for (int i = 0; i < 4; i++) {
        int m0 = bm + wm + (i << 4) + g;
#pragma unroll
        for (int j = 0; j < 4; j++) {
            int n0 = bnG + wn + (j << 3) + 2 * t;
#pragma unroll
            for (int rr = 0; rr < 2; rr++) {
                int m = m0 + rr * 8;
                if (m >= M) continue;
                float v0 = acc[i][j][rr * 2 + 0];
                float v1 = acc[i][j][rr * 2 + 1];
                if (bias) {
                    int bc = bcol + wn + (j << 3) + 2 * t;
                    v0 += bsc * bias[bc];
                    v1 += bsc * bias[bc + 1];
                }
                if (resid) {
                    v0 += resid[(size_t)m * ldr + n0];
                    v1 += resid[(size_t)m * ldr + n0 + 1];
                }
                if (doGelu) {
                    v0 = 0.5f * v0 * (1.0f + erff(v0 * 0.70710678118654752f));
                    v1 = 0.5f * v1 * (1.0f + erff(v1 * 0.70710678118654752f));
                }
                if (roundOut) { v0 = tf32r(v0); v1 = tf32r(v1); }
                *(float2*)(C + (size_t)m * ldc + n0) = make_float2(v0, v1);
            }
        }
    }
}

// ---------------- launch ----------------------------------------------------
extern "C" void kernel_launch(void* const* d_in, const int* in_sizes, int n_in,
                              void* d_out, int out_size) {
    const float* x          = (const float*)d_in[0];
    const float* mask       = (const float*)d_in[1];
    const float* Wg         = (const float*)d_in[2];
    const float* bg         = (const float*)d_in[3];
    const float* log_scales = (const float*)d_in[4];
    const float* Wv         = (const float*)d_in[5];
    const float* bv         = (const float*)d_in[6];
    const float* We         = (const float*)d_in[7];
    const float* be         = (const float*)d_in[8];
    const float* Wo         = (const float*)d_in[9];
    const float* bo         = (const float*)d_in[10];
    const float* ln1g       = (const float*)d_in[11];
    const float* ln1b       = (const float*)d_in[12];
    const float* ln2g       = (const float*)d_in[13];
    const float* ln2b       = (const float*)d_in[14];
    const float* Wf1        = (const float*)d_in[15];
    const float* bf1        = (const float*)d_in[16];
    const float* Wf2        = (const float*)d_in[17];
    const float* bf2        = (const float*)d_in[18];
    float* out = (float*)d_out;

    int B = in_sizes[0] / (KNODES * DMODEL);
    int M = B * KNODES;
    int gy = (M + 127) / 128;

    void *p_xn, *p_P, *p_mats, *p_NE, *p_y, *p_h, *p_F, *p_Wc;
    cudaGetSymbolAddress(&p_xn, g_xn);
    cudaGetSymbolAddress(&p_P, g_P);
    cudaGetSymbolAddress(&p_mats, g_mats);
    cudaGetSymbolAddress(&p_NE, g_NE);
    cudaGetSymbolAddress(&p_y, g_y);
    cudaGetSymbolAddress(&p_h, g_h);
    cudaGetSymbolAddress(&p_F, g_F);
    cudaGetSymbolAddress(&p_Wc, g_Wc);
    float* xn = (float*)p_xn;   float* Pm = (float*)p_P;
    float* mats = (float*)p_mats;
    float* NE = (float*)p_NE;   float* y = (float*)p_y;
    float* h = (float*)p_h;     float* F = (float*)p_F;
    float* Wc = (float*)p_Wc;

    const int smemBytes = SMEM_U32 * 4;  // 75776
    static int attrDone = 0;
    if (!attrDone) {
        cudaFuncSetAttribute(tf32_gemm2, cudaFuncAttributeMaxDynamicSharedMemorySize, smemBytes);
        attrDone = 1;
    }

    const int BIGN = 1 << 28;

    // 0. tf32-round weights into g_Wc
    convert_w_kernel<<<(WTOT + 255) / 256, 256>>>(Wv, We, Wo, Wf1, Wf2, Wc);
    // 1. LN1 + P
    ln1_p_kernel<<<M, 256>>>(x, ln1g, ln1b, Wg, bg, xn, Pm);
    // 2. per-(b,s) 16x16 operators
    build_mats_kernel<<<B, 256>>>(Pm, mask, log_scales, mats);
    // 3+4+5. NE = blockdiag(M) x [xn@Wv + bv | xn@We + 0.5*be]  (fused apply)
    tf32_gemm2<<<dim3(12, gy), 256, smemBytes>>>(
        xn, Wc + OFF_WV, Wc + OFF_WE, 768, 768,
        NE, bv, be, 1.0f, 0.5f, nullptr,
        mats, 1,
        M, 256, 1536, 0, 0, 0);
    // 6. y = x + NE@Wo + bo
    tf32_gemm2<<<dim3(2, gy), 256, smemBytes>>>(
        NE, Wc + OFF_WO, Wc + OFF_WO, BIGN, 256,
        y, bo, bo, 1.0f, 1.0f, x,
        nullptr, 0,
        M, 1536, 256, 256, 0, 0);
    // 7. h = LN2(y)
    ln_kernel<<<M, 256>>>(y, ln2g, ln2b, h);
    // 8. F = gelu(h@Wf1 + bf1)
    tf32_gemm2<<<dim3(8, gy), 256, smemBytes>>>(
        h, Wc + OFF_WF1, Wc + OFF_WF1, BIGN, 1024,
        F, bf1, bf1, 1.0f, 1.0f, nullptr,
        nullptr, 0,
        M, 256, 1024, 0, 1, 1);
    // 9. out = y + F@Wf2 + bf2
    tf32_gemm2<<<dim3(2, gy), 256, smemBytes>>>(
        F, Wc + OFF_WF2, Wc + OFF_WF2, BIGN, 256,
        out, bf2, bf2, 1.0f, 1.0f, y,
        nullptr, 0,
        M, 1024, 256, 256, 0, 0);
}

// round 7
// speedup vs baseline: 3.0366x; 1.1007x over previous
#include <cuda_runtime.h>
#include <cuda_bf16.h>
#include <cstdint>
#include <math.h>

#define KNODES 16
#define DMODEL 256
#define NSCALE 3
#define TAU_C 0.0001f
#define LN_EPS_C 1e-5f
#define MAXB 1024

// weight segment offsets in g_Wc
#define OFF_WV 0
#define OFF_WE 196608
#define OFF_WO 393216
#define OFF_WF1 786432
#define OFF_WF2 1048576
#define WTOT 1310720

// ---------------- scratch (device globals; no allocation allowed) ----------
__device__ float g_xn[MAXB * KNODES * DMODEL];
__device__ float g_P [MAXB * KNODES * KNODES];
__device__ float g_mats[MAXB * NSCALE * 2 * 256];
__device__ float g_NE[(size_t)MAXB * KNODES * 1536];
__device__ float g_y [MAXB * KNODES * DMODEL];
__device__ float g_h [MAXB * KNODES * DMODEL];
__device__ float g_F [(size_t)MAXB * KNODES * 1024];
__device__ float g_Wc[WTOT];

// ---------------- helpers ---------------------------------------------------
__device__ __forceinline__ uint32_t f2tf32(float f) {
    uint32_t r;
    asm("cvt.rna.tf32.f32 %0, %1;" : "=r"(r) : "f"(f));
    return r;
}
__device__ __forceinline__ float tf32r(float f) {
    return __uint_as_float(f2tf32(f));
}
__device__ __forceinline__ uint32_t su32(const void* p) {
    return (uint32_t)__cvta_generic_to_shared(p);
}

__device__ __forceinline__ float block_sum_256(float v) {
    __shared__ float red[8];
#pragma unroll
    for (int o = 16; o > 0; o >>= 1) v += __shfl_xor_sync(0xffffffffu, v, o);
    int lane = threadIdx.x & 31, w = threadIdx.x >> 5;
    if (lane == 0) red[w] = v;
    __syncthreads();
    float t = (threadIdx.x < 8) ? red[threadIdx.x] : 0.f;
    if (threadIdx.x < 32) {
#pragma unroll
        for (int o = 4; o > 0; o >>= 1) t += __shfl_xor_sync(0xffffffffu, t, o);
        if (threadIdx.x == 0) red[0] = t;
    }
    __syncthreads();
    float r = red[0];
    __syncthreads();
    return r;
}

// ---------------- convert weights to tf32-rounded copy ----------------------
__global__ void convert_w_kernel(const float* __restrict__ Wv, const float* __restrict__ We,
                                 const float* __restrict__ Wo, const float* __restrict__ Wf1,
                                 const float* __restrict__ Wf2, float* __restrict__ Wc) {
    int i = blockIdx.x * 256 + threadIdx.x;
    if (i >= WTOT) return;
    float v;
    if (i < OFF_WE)       v = Wv[i];
    else if (i < OFF_WO)  v = We[i - OFF_WE];
    else if (i < OFF_WF1) v = Wo[i - OFF_WO];
    else if (i < OFF_WF2) v = Wf1[i - OFF_WF1];
    else                  v = Wf2[i - OFF_WF2];
    Wc[i] = tf32r(v);
}

// ---------------- LN1 + P = xn @ Wg + bg  (xn stored tf32-rounded) ----------
__global__ void ln1_p_kernel(const float* __restrict__ x,
                             const float* __restrict__ g, const float* __restrict__ bb,
                             const float* __restrict__ Wg, const float* __restrict__ bg,
                             float* __restrict__ xn_out, float* __restrict__ P_out) {
    int row = blockIdx.x;
    int t = threadIdx.x;
    float v = x[(size_t)row * DMODEL + t];
    float mean = block_sum_256(v) * (1.f / DMODEL);
    float d = v - mean;
    float var = block_sum_256(d * d) * (1.f / DMODEL);
    float xn = d * rsqrtf(var + LN_EPS_C) * g[t] + bb[t];
    xn_out[(size_t)row * DMODEL + t] = tf32r(xn);

    __shared__ float sxn[256];
    __shared__ float part[256];
    sxn[t] = xn;
    __syncthreads();
    int c = t & 15, seg = t >> 4;
    float p = 0.f;
    int d0 = seg * 16;
#pragma unroll
    for (int i = 0; i < 16; i++) p += sxn[d0 + i] * Wg[(d0 + i) * 16 + c];
    part[seg * 16 + c] = p;
    __syncthreads();
    if (t < 16) {
        float acc = bg[t];
#pragma unroll
        for (int s = 0; s < 16; s++) acc += part[s * 16 + t];
        P_out[(size_t)row * 16 + t] = acc;
    }
}

// ---------------- plain LN (output tf32-rounded: feeds GEMM) ----------------
__global__ void ln_kernel(const float* __restrict__ x,
                          const float* __restrict__ g, const float* __restrict__ bb,
                          float* __restrict__ out) {
    int row = blockIdx.x;
    int t = threadIdx.x;
    float v = x[(size_t)row * DMODEL + t];
    float mean = block_sum_256(v) * (1.f / DMODEL);
    float d = v - mean;
    float var = block_sum_256(d * d) * (1.f / DMODEL);
    out[(size_t)row * DMODEL + t] = tf32r(d * rsqrtf(var + LN_EPS_C) * g[t] + bb[t]);
}

// ---------------- build per-(b,s) 16x16 operators L0, N --------------------
__global__ void build_mats_kernel(const float* __restrict__ P,
                                  const float* __restrict__ mask,
                                  const float* __restrict__ log_scales,
                                  float* __restrict__ mats) {
    int b = blockIdx.x;
    int tid = threadIdx.x;
    __shared__ float sP[256];
    __shared__ float sm[16];
    __shared__ float sp2[16];
    __shared__ float sDsq[256];
    __shared__ float saff[256];
    __shared__ float stw[16];
    sP[tid] = P[(size_t)b * 256 + tid];
    if (tid < 16) sm[tid] = mask[(size_t)b * 16 + tid];
    __syncthreads();
    int k = tid >> 4, l = tid & 15;
    if (tid < 16) {
        float s = 0.f;
#pragma unroll
        for (int c = 0; c < 16; c++) s += sP[tid * 16 + c] * sP[tid * 16 + c];
        sp2[tid] = s;
    }
    __syncthreads();
    {
        float dt = 0.f;
#pragma unroll
        for (int c = 0; c < 16; c++) dt += sP[k * 16 + c] * sP[l * 16 + c];
        float d2 = sp2[k] + sp2[l] - 2.f * dt;
        sDsq[tid] = fmaxf(d2, 0.f) * sm[k] * sm[l];
    }
    __syncthreads();
    for (int s = 0; s < NSCALE; s++) {
        float denom = 2.f * expf(2.f * log_scales[s]) + 1e-8f;
        saff[tid] = expf(-sDsq[tid] / denom) * sm[k] * sm[l];
        __syncthreads();
        float l0;
        if (k == l) {
            float srow = 0.f;
#pragma unroll
            for (int j = 0; j < 16; j++) if (j != k) srow += saff[k * 16 + j];
            l0 = srow + TAU_C;
        } else {
            l0 = -saff[tid];
        }
        if (tid < 16) {
            float tsum = 0.f;
            int j = tid;
            for (int i = 0; i < j; i++)
                for (int k2 = j + 1; k2 < 16; k2++)
                    tsum += saff[i * 16 + j] * saff[j * 16 + k2] * saff[i * 16 + k2];
            stw[tid] = tsum;
        }
        __syncthreads();
        float nv = 0.f;
#pragma unroll
        for (int kp = 0; kp < 16; kp++) {
            float dk = (kp == k) ? (2.f * k - 15.f) : ((kp > k) ? 1.f : -1.f);
            float dl = (kp == l) ? (2.f * l - 15.f) : ((kp > l) ? 1.f : -1.f);
            nv += sm[kp] * dk * dl;
        }
        nv += (k == l) ? (4.f * stw[k] + 15.f * TAU_C) : TAU_C;
        size_t base = ((size_t)b * NSCALE + s) * 512;
        mats[base + tid]       = l0;
        mats[base + 256 + tid] = nv;
        __syncthreads();
    }
}

// ---------------- tf32 GEMM, cp.async 3-stage pipeline ----------------------
// C(MxN) = A(MxKd) @ B(KdxN) [+ s*bias] [+ resid] [gelu] [tf32-round output]
// applyMats: tensor-core epilogue computes blockdiag(16x16 M) x (acc + bias).
#define ASTRIDE 36
#define BSTRIDE 136
#define CSTRIDE 136
#define STAGE_U32 (128 * ASTRIDE + 32 * BSTRIDE)     // 8960
#define SMEM_U32  (3 * STAGE_U32)                     // 26880 (epilogue fits under)

__global__ __launch_bounds__(256, 2) void tf32_gemm2(
    const float* __restrict__ A,
    const float* __restrict__ B1, const float* __restrict__ B2,
    int N1, int ldb,
    float* __restrict__ C,
    const float* __restrict__ bias1, const float* __restrict__ bias2,
    float s1, float s2,
    const float* __restrict__ resid,
    const float* __restrict__ matsG, int applyMats,
    int M, int Kd, int ldc, int ldr, int doGelu, int roundOut)
{
    extern __shared__ uint32_t sm_[];

    const int tid  = threadIdx.x;
    const int warp = tid >> 5, lane = tid & 31;
    const int g = lane >> 2, t = lane & 3;
    const int wm = (warp & 1) << 6;
    const int wn = (warp >> 1) << 5;
    const int bm = blockIdx.y << 7;
    const int bnG = blockIdx.x << 7;

    const float* Bm; const float* bias; float bsc; int bcol;
    if (bnG < N1) { Bm = B1; bias = bias1; bsc = s1; bcol = bnG; }
    else          { Bm = B2; bias = bias2; bsc = s2; bcol = bnG - N1; }

    float acc[4][4][4];
#pragma unroll
    for (int i = 0; i < 4; i++)
#pragma unroll
        for (int j = 0; j < 4; j++)
#pragma unroll
            for (int r = 0; r < 4; r++) acc[i][j][r] = 0.f;

    const int nCh = Kd >> 5;

#define STAGE(sbuf, k0) do {                                                     \
    uint32_t (*As_)[ASTRIDE] = (uint32_t (*)[ASTRIDE])(sm_ + (sbuf) * STAGE_U32);\
    uint32_t (*Bs_)[BSTRIDE] = (uint32_t (*)[BSTRIDE])(sm_ + (sbuf) * STAGE_U32 + 128 * ASTRIDE); \
    _Pragma("unroll")                                                            \
    for (int i_ = 0; i_ < 4; i_++) {                                             \
        int q_ = tid + (i_ << 8);                                                \
        int r_ = q_ >> 3, kk_ = q_ & 7;                                          \
        int row_ = bm + r_;                                                      \
        int nb_ = (row_ < M) ? 16 : 0;                                           \
        if (row_ >= M) row_ = M - 1;                                             \
        const float* src_ = A + (size_t)row_ * Kd + (k0) + (kk_ << 2);           \
        uint32_t dst_ = su32(&As_[r_][kk_ << 2]);                                \
        asm volatile("cp.async.cg.shared.global [%0], [%1], 16, %2;"             \
                     :: "r"(dst_), "l"(src_), "r"(nb_));                         \
    }                                                                            \
    _Pragma("unroll")                                                            \
    for (int i_ = 0; i_ < 4; i_++) {                                             \
        int q_ = tid + (i_ << 8);                                                \
        int r_ = q_ >> 5, cc_ = (q_ & 31) << 2;                                  \
        const float* src_ = Bm + (size_t)((k0) + r_) * ldb + bcol + cc_;         \
        uint32_t dst_ = su32(&Bs_[r_][cc_]);                                     \
        asm volatile("cp.async.cg.shared.global [%0], [%1], 16;"                 \
                     :: "r"(dst_), "l"(src_));                                   \
    }                                                                            \
    asm volatile("cp.async.commit_group;");                                      \
} while (0)

    STAGE(0, 0);
    if (nCh > 1) STAGE(1, 32);

    int sCur = 0, sNext2 = 2;
    for (int ch = 0; ch < nCh; ch++) {
        if (ch + 1 < nCh) asm volatile("cp.async.wait_group 1;" ::: "memory");
        else              asm volatile("cp.async.wait_group 0;" ::: "memory");
        __syncthreads();
        if (ch + 2 < nCh) STAGE(sNext2, (ch + 2) << 5);

        uint32_t (*As)[ASTRIDE] = (uint32_t (*)[ASTRIDE])(sm_ + sCur * STAGE_U32);
        uint32_t (*Bs)[BSTRIDE] = (uint32_t (*)[BSTRIDE])(sm_ + sCur * STAGE_U32 + 128 * ASTRIDE);

#pragma unroll
        for (int kc = 0; kc < 4; kc++) {
            const int kr = (kc << 3) + t;
            uint32_t af[4][4], bf[4][2];
#pragma unroll
            for (int i = 0; i < 4; i++) {
                int m = wm + (i << 4) + g;
                af[i][0] = As[m][kr];
                af[i][1] = As[m + 8][kr];
                af[i][2] = As[m][kr + 4];
                af[i][3] = As[m + 8][kr + 4];
            }
#pragma unroll
            for (int j = 0; j < 4; j++) {
                int n = wn + (j << 3) + g;
                bf[j][0] = Bs[kr][n];
                bf[j][1] = Bs[kr + 4][n];
            }
#pragma unroll
            for (int i = 0; i < 4; i++)
#pragma unroll
                for (int j = 0; j < 4; j++) {
                    asm volatile(
                        "mma.sync.aligned.m16n8k8.row.col.f32.tf32.tf32.f32 "
                        "{%0,%1,%2,%3}, {%4,%5,%6,%7}, {%8,%9}, {%0,%1,%2,%3};"
                        : "+f"(acc[i][j][0]), "+f"(acc[i][j][1]),
                          "+f"(acc[i][j][2]), "+f"(acc[i][j][3])
                        : "r"(af[i][0]), "r"(af[i][1]), "r"(af[i][2]), "r"(af[i][3]),
                          "r"(bf[j][0]), "r"(bf[j][1]));
                }
        }
        sCur = (sCur == 2) ? 0 : sCur + 1;
        sNext2 = (sNext2 == 2) ? 0 : sNext2 + 1;
    }
#undef STAGE

    if (applyMats) {
        // tensor-core 16x16 operator application:  out_b = M_b @ (acc_b + bias)
        float (*Cs)[CSTRIDE] = (float (*)[CSTRIDE])sm_;
        float* matS = (float*)(sm_ + 128 * CSTRIDE);
        __syncthreads();   // done with stage buffers
        // stage biased accumulators (tf32-rounded) into smem tile
#pragma unroll
        for (int i = 0; i < 4; i++) {
            int ml = wm + (i << 4) + g;
#pragma unroll
            for (int j = 0; j < 4; j++) {
                int nl = wn + (j << 3) + 2 * t;
                int bc = bcol + nl;
                float b0v = bias ? bsc * bias[bc]     : 0.f;
                float b1v = bias ? bsc * bias[bc + 1] : 0.f;
#pragma unroll
                for (int rr = 0; rr < 2; rr++) {
                    float2 vv = make_float2(tf32r(acc[i][j][rr * 2 + 0] + b0v),
                                            tf32r(acc[i][j][rr * 2 + 1] + b1v));
                    *(float2*)&Cs[ml + rr * 8][nl] = vv;
                }
            }
        }
        // load the 8 per-batch 16x16 matrices (tf32-rounded)
        int isN = (bnG >= 768) ? 1 : 0;
        int sgrp = (isN ? (bnG - 768) : bnG) >> 8;
        int b0 = bm >> 4;
        for (int i = tid; i < 2048; i += 256) {
            int bb = i >> 8, e = i & 255;
            matS[i] = tf32r(matsG[((size_t)(b0 + bb) * NSCALE + sgrp) * 512 + (isN << 8) + e]);
        }
        __syncthreads();
        // warp bb handles batch bb via mma: A = M_b (16x16), B = Cs rows
        const int bb = warp;
        const float* Mb = matS + (bb << 8);
        const int rowBase = bb << 4;
        const int growBase = bm + rowBase;
        uint32_t a[2][4];
#pragma unroll
        for (int ks = 0; ks < 2; ks++) {
            int kk = ks << 3;
            a[ks][0] = __float_as_uint(Mb[(g << 4) + kk + t]);
            a[ks][1] = __float_as_uint(Mb[((g + 8) << 4) + kk + t]);
            a[ks][2] = __float_as_uint(Mb[(g << 4) + kk + t + 4]);
            a[ks][3] = __float_as_uint(Mb[((g + 8) << 4) + kk + t + 4]);
        }
        if (growBase < M) {
#pragma unroll
            for (int nn = 0; nn < 16; nn++) {
                int n0 = nn << 3;
                float c0 = 0.f, c1 = 0.f, c2 = 0.f, c3 = 0.f;
#pragma unroll
                for (int ks = 0; ks < 2; ks++) {
                    uint32_t b0r = __float_as_uint(Cs[rowBase + (ks << 3) + t][n0 + g]);
                    uint32_t b1r = __float_as_uint(Cs[rowBase + (ks << 3) + t + 4][n0 + g]);
                    asm volatile(
                        "mma.sync.aligned.m16n8k8.row.col.f32.tf32.tf32.f32 "
                        "{%0,%1,%2,%3}, {%4,%5,%6,%7}, {%8,%9}, {%0,%1,%2,%3};"
                        : "+f"(c0), "+f"(c1), "+f"(c2), "+f"(c3)
                        : "r"(a[ks][0]), "r"(a[ks][1]), "r"(a[ks][2]), "r"(a[ks][3]),
                          "r"(b0r), "r"(b1r));
                }
                int colG = bnG + n0 + 2 * t;
                *(float2*)(C + (size_t)(growBase + g) * ldc + colG) =
                    make_float2(tf32r(c0), tf32r(c1));
                *(float2*)(C + (size_t)(growBase + g + 8) * ldc + colG) =
                    make_float2(tf32r(c2), tf32r(c3));
            }
        }
        return;
    }

    // generic epilogue
#pragma unroll
    for (int i = 0; i < 4; i++) {
        int m0 = bm + wm + (i << 4) + g;
#pragma unroll
        for (int j = 0; j < 4; j++) {
            int n0 = bnG + wn + (j << 3) + 2 * t;
#pragma unroll
            for (int rr = 0; rr < 2; rr++) {
                int m = m0 + rr * 8;
                if (m >= M) continue;
                float v0 = acc[i][j][rr * 2 + 0];
                float v1 = acc[i][j][rr * 2 + 1];
                if (bias) {
                    int bc = bcol + wn + (j << 3) + 2 * t;
                    v0 += bsc * bias[bc];
                    v1 += bsc * bias[bc + 1];
                }
                if (resid) {
                    v0 += resid[(size_t)m * ldr + n0];
                    v1 += resid[(size_t)m * ldr + n0 + 1];
                }
                if (doGelu) {
                    v0 = 0.5f * v0 * (1.0f + erff(v0 * 0.70710678118654752f));
                    v1 = 0.5f * v1 * (1.0f + erff(v1 * 0.70710678118654752f));
                }
                if (roundOut) { v0 = tf32r(v0); v1 = tf32r(v1); }
                *(float2*)(C + (size_t)m * ldc + n0) = make_float2(v0, v1);
            }
        }
    }
}

// ---------------- launch ----------------------------------------------------
extern "C" void kernel_launch(void* const* d_in, const int* in_sizes, int n_in,
                              void* d_out, int out_size) {
    const float* x          = (const float*)d_in[0];
    const float* mask       = (const float*)d_in[1];
    const float* Wg         = (const float*)d_in[2];
    const float* bg         = (const float*)d_in[3];
    const float* log_scales = (const float*)d_in[4];
    const float* Wv         = (const float*)d_in[5];
    const float* bv         = (const float*)d_in[6];
    const float* We         = (const float*)d_in[7];
    const float* be         = (const float*)d_in[8];
    const float* Wo         = (const float*)d_in[9];
    const float* bo         = (const float*)d_in[10];
    const float* ln1g       = (const float*)d_in[11];
    const float* ln1b       = (const float*)d_in[12];
    const float* ln2g       = (const float*)d_in[13];
    const float* ln2b       = (const float*)d_in[14];
    const float* Wf1        = (const float*)d_in[15];
    const float* bf1        = (const float*)d_in[16];
    const float* Wf2        = (const float*)d_in[17];
    const float* bf2        = (const float*)d_in[18];
    float* out = (float*)d_out;

    int B = in_sizes[0] / (KNODES * DMODEL);
    int M = B * KNODES;
    int gy = (M + 127) / 128;

    void *p_xn, *p_P, *p_mats, *p_NE, *p_y, *p_h, *p_F, *p_Wc;
    cudaGetSymbolAddress(&p_xn, g_xn);
    cudaGetSymbolAddress(&p_P, g_P);
    cudaGetSymbolAddress(&p_mats, g_mats);
    cudaGetSymbolAddress(&p_NE, g_NE);
    cudaGetSymbolAddress(&p_y, g_y);
    cudaGetSymbolAddress(&p_h, g_h);
    cudaGetSymbolAddress(&p_F, g_F);
    cudaGetSymbolAddress(&p_Wc, g_Wc);
    float* xn = (float*)p_xn;   float* Pm = (float*)p_P;
    float* mats = (float*)p_mats;
    float* NE = (float*)p_NE;   float* y = (float*)p_y;
    float* h = (float*)p_h;     float* F = (float*)p_F;
    float* Wc = (float*)p_Wc;

    const int smemBytes = SMEM_U32 * 4;  // 107520
    static int attrDone = 0;
    if (!attrDone) {
        cudaFuncSetAttribute(tf32_gemm2, cudaFuncAttributeMaxDynamicSharedMemorySize, smemBytes);
        attrDone = 1;
    }

    const int BIGN = 1 << 28;

    // 0. tf32-round weights into g_Wc
    convert_w_kernel<<<(WTOT + 255) / 256, 256>>>(Wv, We, Wo, Wf1, Wf2, Wc);
    // 1. LN1 + P
    ln1_p_kernel<<<M, 256>>>(x, ln1g, ln1b, Wg, bg, xn, Pm);
    // 2. per-(b,s) 16x16 operators
    build_mats_kernel<<<B, 256>>>(Pm, mask, log_scales, mats);
    // 3+4+5. NE = blockdiag(M) x [xn@Wv + bv | xn@We + 0.5*be]  (fused apply)
    tf32_gemm2<<<dim3(12, gy), 256, smemBytes>>>(
        xn, Wc + OFF_WV, Wc + OFF_WE, 768, 768,
        NE, bv, be, 1.0f, 0.5f, nullptr,
        mats, 1,
        M, 256, 1536, 0, 0, 0);
    // 6. y = x + NE@Wo + bo
    tf32_gemm2<<<dim3(2, gy), 256, smemBytes>>>(
        NE, Wc + OFF_WO, Wc + OFF_WO, BIGN, 256,
        y, bo, bo, 1.0f, 1.0f, x,
        nullptr, 0,
        M, 1536, 256, 256, 0, 0);
    // 7. h = LN2(y)
    ln_kernel<<<M, 256>>>(y, ln2g, ln2b, h);
    // 8. F = gelu(h@Wf1 + bf1)
    tf32_gemm2<<<dim3(8, gy), 256, smemBytes>>>(
        h, Wc + OFF_WF1, Wc + OFF_WF1, BIGN, 1024,
        F, bf1, bf1, 1.0f, 1.0f, nullptr,
        nullptr, 0,
        M, 256, 1024, 0, 1, 1);
    // 9. out = y + F@Wf2 + bf2
    tf32_gemm2<<<dim3(2, gy), 256, smemBytes>>>(
        F, Wc + OFF_WF2, Wc + OFF_WF2, BIGN, 256,
        out, bf2, bf2, 1.0f, 1.0f, y,
        nullptr, 0,
        M, 1024, 256, 256, 0, 0);
}